// round 13
// baseline (speedup 1.0000x reference)
#include <cuda_runtime.h>
#include <math.h>

#define NUM_RADIUS 15
#define NUM_ANGLE 48
#define EMB 32
#define NUM_ACTIONS 4
#define TPB 256

// LR[r][a] = sum_e radius_table[r][e] * W[e][a]
// LA[t][a] = sum_e angle_table[t][e]  * W[32+e][a] + b[a]
__device__ float g_LR[NUM_RADIUS * NUM_ACTIONS];
__device__ float g_LA[NUM_ANGLE * NUM_ACTIONS];

// Warp-per-output precompute: 252 outputs, one warp each (32 blocks x 8 warps).
__global__ void __launch_bounds__(TPB)
precompute_tables_kernel(const float* __restrict__ radius_table,
                         const float* __restrict__ angle_table,
                         const float* __restrict__ W,
                         const float* __restrict__ b) {
    int warp = (blockIdx.x * TPB + threadIdx.x) >> 5;   // 0..255
    int lane = threadIdx.x & 31;
    const int NLR = NUM_RADIUS * NUM_ACTIONS;   // 60
    const int NLA = NUM_ANGLE * NUM_ACTIONS;    // 192

    float v = 0.0f;
    bool is_lr = warp < NLR;
    bool is_la = !is_lr && warp < NLR + NLA;
    if (is_lr) {
        int row = warp >> 2, a = warp & 3;
        v = radius_table[row * EMB + lane] * W[lane * NUM_ACTIONS + a];
    } else if (is_la) {
        int k = warp - NLR;
        int row = k >> 2, a = k & 3;
        v = angle_table[row * EMB + lane] * W[(EMB + lane) * NUM_ACTIONS + a];
        if (lane == 0) v += b[a];
    }
    #pragma unroll
    for (int off = 16; off > 0; off >>= 1)
        v += __shfl_down_sync(0xffffffffu, v, off);

    if (lane == 0) {
        if (is_lr) g_LR[warp] = v;
        else if (is_la) g_LA[warp - NLR] = v;
    }
}

// Fast atan2: half-angle reduction + Taylor through u^13.
// Total error ~1e-6 rad including division rounding.
__device__ __forceinline__ float fast_atan2f(float y, float x) {
    float ax = fabsf(x), ay = fabsf(y);
    float mn = fminf(ax, ay), mx = fmaxf(ax, ay);
    float t = __fdividef(mn, mx);                          // [0,1]
    float r = sqrtf(fmaf(t, t, 1.0f));                     // [1, 1.414]
    float u = __fdividef(t, 1.0f + r);                     // [0, 0.4142]
    float s = u * u;
    float p = 0.07692307693f;                 //  1/13
    p = fmaf(p, s, -0.09090909091f);          // -1/11
    p = fmaf(p, s,  0.11111111111f);          //  1/9
    p = fmaf(p, s, -0.14285714286f);          // -1/7
    p = fmaf(p, s,  0.2f);                    //  1/5
    p = fmaf(p, s, -0.33333333333f);          // -1/3
    float atu = fmaf(p * s, u, u);            // atan(u)
    float a = 2.0f * atu;                     // atan(t)
    if (ay > ax) a = 1.57079632679f - a;
    if (x < 0.0f) a = 3.14159265359f - a;
    return (y < 0.0f) ? -a : a;
}

__device__ __forceinline__ float4 process_row(float axp, float azp, float pose,
                                              float gx, float gz,
                                              const float* __restrict__ sLR,
                                              const float* __restrict__ sLA) {
    float dx = gx - axp;
    float dz = gz - azp;

    // radius bucket
    float radius = sqrtf(fmaf(dx, dx, dz * dz));
    int r_idx = (int)(radius * 0.2f);
    r_idx = max(0, min(r_idx, NUM_RADIUS - 1));

    // angle bucket: match reference rounding (separate mul then sub, no fma)
    float deg = __fmul_rn(fast_atan2f(dz, dx), 57.29577951308232f);
    float dtg = __fsub_rn(90.0f, deg);
    float f = __fsub_rn(dtg, pose);
    float ad = fmaf(-360.0f, floorf(f * 0.0027777778f), f);
    ad = fminf(fmaxf(ad, 0.0f), 359.99997f);
    int t_idx = (int)(ad * 0.13333334f);
    t_idx = max(0, min(t_idx, NUM_ANGLE - 1));

    const float* lr = &sLR[r_idx * NUM_ACTIONS];
    const float* la = &sLA[t_idx * NUM_ACTIONS];
    float l0 = lr[0] + la[0];
    float l1 = lr[1] + la[1];
    float l2 = lr[2] + la[2];
    float l3 = lr[3] + la[3];

    // log_softmax WITHOUT max-shift: |logit| < ~1.5 (tables ~N(0,0.1) dots),
    // so exp can't overflow; the shift is cosmetic here.
    float e0 = __expf(l0);
    float e1 = __expf(l1);
    float e2 = __expf(l2);
    float e3 = __expf(l3);
    float lse = __logf(e0 + e1 + e2 + e3);

    return make_float4(l0 - lse, l1 - lse, l2 - lse, l3 - lse);
}

__global__ void __launch_bounds__(TPB)
goal_position_kernel(const float4* __restrict__ agent4,  // [B,3] as float4s
                     const float4* __restrict__ goal4,   // [B,2] as float4s
                     float4* __restrict__ out,           // [B,4]
                     int n8) {                            // n/8
    __shared__ float sLR[NUM_RADIUS * NUM_ACTIONS];
    __shared__ float sLA[NUM_ANGLE * NUM_ACTIONS];
    int t = threadIdx.x;
    if (t < NUM_RADIUS * NUM_ACTIONS) sLR[t] = g_LR[t];
    if (t < NUM_ANGLE * NUM_ACTIONS) sLA[t] = g_LA[t];
    __syncthreads();

    int i = blockIdx.x * blockDim.x + t;
    if (i >= n8) return;

    // 8 rows per thread: batch-issue 10 LDG.128 (6 agent + 4 goal)
    float4 a0 = agent4[6 * i + 0];   // x0 z0 p0 x1
    float4 a1 = agent4[6 * i + 1];   // z1 p1 x2 z2
    float4 a2 = agent4[6 * i + 2];   // p2 x3 z3 p3
    float4 a3 = agent4[6 * i + 3];   // x4 z4 p4 x5
    float4 a4 = agent4[6 * i + 4];   // z5 p5 x6 z6
    float4 a5 = agent4[6 * i + 5];   // p6 x7 z7 p7
    float4 g0 = goal4[4 * i + 0];    // gx0 gz0 gx1 gz1
    float4 g1 = goal4[4 * i + 1];    // gx2 gz2 gx3 gz3
    float4 g2 = goal4[4 * i + 2];    // gx4 gz4 gx5 gz5
    float4 g3 = goal4[4 * i + 3];    // gx6 gz6 gx7 gz7

    float4 o0 = process_row(a0.x, a0.y, a0.z, g0.x, g0.y, sLR, sLA);
    float4 o1 = process_row(a0.w, a1.x, a1.y, g0.z, g0.w, sLR, sLA);
    float4 o2 = process_row(a1.z, a1.w, a2.x, g1.x, g1.y, sLR, sLA);
    float4 o3 = process_row(a2.y, a2.z, a2.w, g1.z, g1.w, sLR, sLA);
    float4 o4 = process_row(a3.x, a3.y, a3.z, g2.x, g2.y, sLR, sLA);
    float4 o5 = process_row(a3.w, a4.x, a4.y, g2.z, g2.w, sLR, sLA);
    float4 o6 = process_row(a4.z, a4.w, a5.x, g3.x, g3.y, sLR, sLA);
    float4 o7 = process_row(a5.y, a5.z, a5.w, g3.z, g3.w, sLR, sLA);

    out[8 * i + 0] = o0;
    out[8 * i + 1] = o1;
    out[8 * i + 2] = o2;
    out[8 * i + 3] = o3;
    out[8 * i + 4] = o4;
    out[8 * i + 5] = o5;
    out[8 * i + 6] = o6;
    out[8 * i + 7] = o7;
}

extern "C" void kernel_launch(void* const* d_in, const int* in_sizes, int n_in,
                              void* d_out, int out_size) {
    const float* agent = (const float*)d_in[0];   // [B,3]
    const float* goal = (const float*)d_in[1];    // [B,2]
    const float* radius_table = (const float*)d_in[2];
    const float* angle_table = (const float*)d_in[3];
    const float* W = (const float*)d_in[4];
    const float* b = (const float*)d_in[5];

    int n = in_sizes[0] / 3;    // B = 2,000,000 (divisible by 8)
    int n8 = n / 8;

    precompute_tables_kernel<<<32, TPB>>>(radius_table, angle_table, W, b);

    int blocks = (n8 + TPB - 1) / TPB;   // 977
    goal_position_kernel<<<blocks, TPB>>>((const float4*)agent,
                                          (const float4*)goal,
                                          (float4*)d_out, n8);
}

// round 14
// speedup vs baseline: 1.2000x; 1.2000x over previous
#include <cuda_runtime.h>
#include <math.h>

#define NUM_RADIUS 15
#define NUM_ANGLE 48
#define EMB 32
#define NUM_ACTIONS 4
#define TPB 256

// LR[r] = (float4) logit contribution of radius bucket r
// LA[t] = (float4) logit contribution of angle bucket t (+ bias)
__device__ float4 g_LR4[NUM_RADIUS];
__device__ float4 g_LA4[NUM_ANGLE];

// Warp-per-output precompute: 252 outputs, one warp each (32 blocks x 8 warps).
__global__ void __launch_bounds__(TPB)
precompute_tables_kernel(const float* __restrict__ radius_table,
                         const float* __restrict__ angle_table,
                         const float* __restrict__ W,
                         const float* __restrict__ b) {
    int warp = (blockIdx.x * TPB + threadIdx.x) >> 5;   // 0..255
    int lane = threadIdx.x & 31;
    const int NLR = NUM_RADIUS * NUM_ACTIONS;   // 60
    const int NLA = NUM_ANGLE * NUM_ACTIONS;    // 192

    float v = 0.0f;
    bool is_lr = warp < NLR;
    bool is_la = !is_lr && warp < NLR + NLA;
    if (is_lr) {
        int row = warp >> 2, a = warp & 3;
        v = radius_table[row * EMB + lane] * W[lane * NUM_ACTIONS + a];
    } else if (is_la) {
        int k = warp - NLR;
        int row = k >> 2, a = k & 3;
        v = angle_table[row * EMB + lane] * W[(EMB + lane) * NUM_ACTIONS + a];
        if (lane == 0) v += b[a];
    }
    #pragma unroll
    for (int off = 16; off > 0; off >>= 1)
        v += __shfl_down_sync(0xffffffffu, v, off);

    if (lane == 0) {
        if (is_lr) ((float*)g_LR4)[warp] = v;
        else if (is_la) ((float*)g_LA4)[warp - NLR] = v;
    }
}

// Fast atan2: half-angle reduction + Taylor through u^13.
// Total error ~1e-6 rad including division rounding.
__device__ __forceinline__ float fast_atan2f(float y, float x) {
    float ax = fabsf(x), ay = fabsf(y);
    float mn = fminf(ax, ay), mx = fmaxf(ax, ay);
    float t = __fdividef(mn, mx);                          // [0,1]
    float r = sqrtf(fmaf(t, t, 1.0f));                     // [1, 1.414]
    float u = __fdividef(t, 1.0f + r);                     // [0, 0.4142]
    float s = u * u;
    float p = 0.07692307693f;                 //  1/13
    p = fmaf(p, s, -0.09090909091f);          // -1/11
    p = fmaf(p, s,  0.11111111111f);          //  1/9
    p = fmaf(p, s, -0.14285714286f);          // -1/7
    p = fmaf(p, s,  0.2f);                    //  1/5
    p = fmaf(p, s, -0.33333333333f);          // -1/3
    float atu = fmaf(p * s, u, u);            // atan(u)
    float a = 2.0f * atu;                     // atan(t)
    if (ay > ax) a = 1.57079632679f - a;
    if (x < 0.0f) a = 3.14159265359f - a;
    return (y < 0.0f) ? -a : a;
}

__device__ __forceinline__ float4 process_row(float axp, float azp, float pose,
                                              float gx, float gz,
                                              const float4* __restrict__ sLR4,
                                              const float4* __restrict__ sLA4) {
    float dx = gx - axp;
    float dz = gz - azp;

    // radius bucket
    float radius = sqrtf(fmaf(dx, dx, dz * dz));
    int r_idx = (int)(radius * 0.2f);
    r_idx = max(0, min(r_idx, NUM_RADIUS - 1));

    // angle bucket: match reference rounding (separate mul then sub, no fma)
    float deg = __fmul_rn(fast_atan2f(dz, dx), 57.29577951308232f);
    float dtg = __fsub_rn(90.0f, deg);
    float f = __fsub_rn(dtg, pose);
    float ad = fmaf(-360.0f, floorf(f * 0.0027777778f), f);
    ad = fminf(fmaxf(ad, 0.0f), 359.99997f);
    int t_idx = (int)(ad * 0.13333334f);
    t_idx = max(0, min(t_idx, NUM_ANGLE - 1));

    // 2 LDS.128 instead of 8 LDS.32 (fewer instrs, far fewer bank-conflict
    // wavefronts: random scalar reads of these layouts were 2-4 way conflicted)
    float4 lr = sLR4[r_idx];
    float4 la = sLA4[t_idx];
    float l0 = lr.x + la.x;
    float l1 = lr.y + la.y;
    float l2 = lr.z + la.z;
    float l3 = lr.w + la.w;

    // log_softmax WITHOUT max-shift: |logit| < ~1.5 (tables ~N(0,0.1) dots),
    // so exp can't overflow; the shift is cosmetic here.
    float e0 = __expf(l0);
    float e1 = __expf(l1);
    float e2 = __expf(l2);
    float e3 = __expf(l3);
    float lse = __logf(e0 + e1 + e2 + e3);

    return make_float4(l0 - lse, l1 - lse, l2 - lse, l3 - lse);
}

__global__ void __launch_bounds__(TPB, 8)   // regs<=32 -> 8 blocks/SM
goal_position_kernel(const float4* __restrict__ agent4,  // [B,3] as float4s
                     const float4* __restrict__ goal4,   // [B,2] as float4s
                     float4* __restrict__ out,           // [B,4]
                     int n4) {                            // n/4
    __shared__ float4 sLR4[NUM_RADIUS];
    __shared__ float4 sLA4[NUM_ANGLE];
    int t = threadIdx.x;
    if (t < NUM_RADIUS) sLR4[t] = g_LR4[t];
    if (t < NUM_ANGLE) sLA4[t] = g_LA4[t];
    __syncthreads();

    int i = blockIdx.x * blockDim.x + t;
    if (i >= n4) return;

    // 4 rows per thread: 5 batched LDG.128 (MLP=5)
    float4 a0 = agent4[3 * i + 0];   // x0 z0 p0 x1
    float4 a1 = agent4[3 * i + 1];   // z1 p1 x2 z2
    float4 a2 = agent4[3 * i + 2];   // p2 x3 z3 p3
    float4 g0 = goal4[2 * i + 0];    // gx0 gz0 gx1 gz1
    float4 g1 = goal4[2 * i + 1];    // gx2 gz2 gx3 gz3

    float4 o0 = process_row(a0.x, a0.y, a0.z, g0.x, g0.y, sLR4, sLA4);
    float4 o1 = process_row(a0.w, a1.x, a1.y, g0.z, g0.w, sLR4, sLA4);
    float4 o2 = process_row(a1.z, a1.w, a2.x, g1.x, g1.y, sLR4, sLA4);
    float4 o3 = process_row(a2.y, a2.z, a2.w, g1.z, g1.w, sLR4, sLA4);

    out[4 * i + 0] = o0;
    out[4 * i + 1] = o1;
    out[4 * i + 2] = o2;
    out[4 * i + 3] = o3;
}

extern "C" void kernel_launch(void* const* d_in, const int* in_sizes, int n_in,
                              void* d_out, int out_size) {
    const float* agent = (const float*)d_in[0];   // [B,3]
    const float* goal = (const float*)d_in[1];    // [B,2]
    const float* radius_table = (const float*)d_in[2];
    const float* angle_table = (const float*)d_in[3];
    const float* W = (const float*)d_in[4];
    const float* b = (const float*)d_in[5];

    int n = in_sizes[0] / 3;    // B = 2,000,000 (divisible by 4)
    int n4 = n / 4;

    precompute_tables_kernel<<<32, TPB>>>(radius_table, angle_table, W, b);

    int blocks = (n4 + TPB - 1) / TPB;   // 1954
    goal_position_kernel<<<blocks, TPB>>>((const float4*)agent,
                                          (const float4*)goal,
                                          (float4*)d_out, n4);
}

// round 15
// speedup vs baseline: 1.3483x; 1.1236x over previous
#include <cuda_runtime.h>
#include <math.h>

#define NUM_RADIUS 15
#define NUM_ANGLE 48
#define EMB 32
#define NUM_ACTIONS 4
#define TPB 256
#define ROWS_PER_BLOCK (TPB * 4)   // 1024

// LR[r] = (float4) logit contribution of radius bucket r
// LA[t] = (float4) logit contribution of angle bucket t (+ bias)
__device__ float4 g_LR4[NUM_RADIUS];
__device__ float4 g_LA4[NUM_ANGLE];

// Warp-per-output precompute: 252 outputs, one warp each (32 blocks x 8 warps).
__global__ void __launch_bounds__(TPB)
precompute_tables_kernel(const float* __restrict__ radius_table,
                         const float* __restrict__ angle_table,
                         const float* __restrict__ W,
                         const float* __restrict__ b) {
    int warp = (blockIdx.x * TPB + threadIdx.x) >> 5;   // 0..255
    int lane = threadIdx.x & 31;
    const int NLR = NUM_RADIUS * NUM_ACTIONS;   // 60
    const int NLA = NUM_ANGLE * NUM_ACTIONS;    // 192

    float v = 0.0f;
    bool is_lr = warp < NLR;
    bool is_la = !is_lr && warp < NLR + NLA;
    if (is_lr) {
        int row = warp >> 2, a = warp & 3;
        v = radius_table[row * EMB + lane] * W[lane * NUM_ACTIONS + a];
    } else if (is_la) {
        int k = warp - NLR;
        int row = k >> 2, a = k & 3;
        v = angle_table[row * EMB + lane] * W[(EMB + lane) * NUM_ACTIONS + a];
        if (lane == 0) v += b[a];
    }
    #pragma unroll
    for (int off = 16; off > 0; off >>= 1)
        v += __shfl_down_sync(0xffffffffu, v, off);

    if (lane == 0) {
        if (is_lr) ((float*)g_LR4)[warp] = v;
        else if (is_la) ((float*)g_LA4)[warp - NLR] = v;
    }
}

// Fast atan2: half-angle reduction + Taylor through u^13.
// Total error ~1e-6 rad including division rounding.
__device__ __forceinline__ float fast_atan2f(float y, float x) {
    float ax = fabsf(x), ay = fabsf(y);
    float mn = fminf(ax, ay), mx = fmaxf(ax, ay);
    float t = __fdividef(mn, mx);                          // [0,1]
    float r = sqrtf(fmaf(t, t, 1.0f));                     // [1, 1.414]
    float u = __fdividef(t, 1.0f + r);                     // [0, 0.4142]
    float s = u * u;
    float p = 0.07692307693f;                 //  1/13
    p = fmaf(p, s, -0.09090909091f);          // -1/11
    p = fmaf(p, s,  0.11111111111f);          //  1/9
    p = fmaf(p, s, -0.14285714286f);          // -1/7
    p = fmaf(p, s,  0.2f);                    //  1/5
    p = fmaf(p, s, -0.33333333333f);          // -1/3
    float atu = fmaf(p * s, u, u);            // atan(u)
    float a = 2.0f * atu;                     // atan(t)
    if (ay > ax) a = 1.57079632679f - a;
    if (x < 0.0f) a = 3.14159265359f - a;
    return (y < 0.0f) ? -a : a;
}

__device__ __forceinline__ float4 process_row(float axp, float azp, float pose,
                                              float gx, float gz,
                                              const float4* __restrict__ sLR4,
                                              const float4* __restrict__ sLA4) {
    float dx = gx - axp;
    float dz = gz - azp;

    // radius bucket
    float radius = sqrtf(fmaf(dx, dx, dz * dz));
    int r_idx = (int)(radius * 0.2f);
    r_idx = max(0, min(r_idx, NUM_RADIUS - 1));

    // angle bucket: match reference rounding (separate mul then sub, no fma)
    float deg = __fmul_rn(fast_atan2f(dz, dx), 57.29577951308232f);
    float dtg = __fsub_rn(90.0f, deg);
    float f = __fsub_rn(dtg, pose);
    float ad = fmaf(-360.0f, floorf(f * 0.0027777778f), f);
    ad = fminf(fmaxf(ad, 0.0f), 359.99997f);
    int t_idx = (int)(ad * 0.13333334f);
    t_idx = max(0, min(t_idx, NUM_ANGLE - 1));

    float4 lr = sLR4[r_idx];   // LDS.128
    float4 la = sLA4[t_idx];   // LDS.128
    float l0 = lr.x + la.x;
    float l1 = lr.y + la.y;
    float l2 = lr.z + la.z;
    float l3 = lr.w + la.w;

    // log_softmax WITHOUT max-shift: |logit| < ~1.5, exp cannot overflow.
    float e0 = __expf(l0);
    float e1 = __expf(l1);
    float e2 = __expf(l2);
    float e3 = __expf(l3);
    float lse = __logf(e0 + e1 + e2 + e3);

    return make_float4(l0 - lse, l1 - lse, l2 - lse, l3 - lse);
}

// Row mapping for coalescing: block owns rows [R, R+1024); thread t handles
// rows R+t, R+256+t, R+512+t, R+768+t. All goal loads (LDG.64) and out
// stores (STG.128) are lane-contiguous -> minimal L1 wavefronts.
// Agent is 12B/row -> 3 scalar LDG.32 per row (3 wf each, irreducible).
__global__ void __launch_bounds__(TPB, 8)
goal_position_kernel(const float* __restrict__ agentF,   // [B*3]
                     const float2* __restrict__ goal2,   // [B]
                     float4* __restrict__ out,           // [B]
                     int n) {                             // B
    __shared__ float4 sLR4[NUM_RADIUS];
    __shared__ float4 sLA4[NUM_ANGLE];
    int t = threadIdx.x;
    if (t < NUM_RADIUS) sLR4[t] = g_LR4[t];
    if (t < NUM_ANGLE) sLA4[t] = g_LA4[t];
    __syncthreads();

    int R = blockIdx.x * ROWS_PER_BLOCK;
    int r0 = R + t;
    int r1 = r0 + TPB;
    int r2 = r1 + TPB;
    int r3 = r2 + TPB;

    bool v0 = r0 < n, v1 = r1 < n, v2 = r2 < n, v3 = r3 < n;

    // Batch-issue all loads (MLP: up to 16 outstanding)
    float x0 = 0.f, z0 = 0.f, p0 = 0.f, x1 = 0.f, z1 = 0.f, p1 = 0.f;
    float x2 = 0.f, z2 = 0.f, p2 = 0.f, x3 = 0.f, z3 = 0.f, p3 = 0.f;
    float2 g0 = make_float2(0.f, 0.f), g1 = g0, g2 = g0, g3 = g0;

    if (v0) { x0 = agentF[3*r0]; z0 = agentF[3*r0+1]; p0 = agentF[3*r0+2]; g0 = goal2[r0]; }
    if (v1) { x1 = agentF[3*r1]; z1 = agentF[3*r1+1]; p1 = agentF[3*r1+2]; g1 = goal2[r1]; }
    if (v2) { x2 = agentF[3*r2]; z2 = agentF[3*r2+1]; p2 = agentF[3*r2+2]; g2 = goal2[r2]; }
    if (v3) { x3 = agentF[3*r3]; z3 = agentF[3*r3+1]; p3 = agentF[3*r3+2]; g3 = goal2[r3]; }

    float4 o0 = process_row(x0, z0, p0, g0.x, g0.y, sLR4, sLA4);
    float4 o1 = process_row(x1, z1, p1, g1.x, g1.y, sLR4, sLA4);
    float4 o2 = process_row(x2, z2, p2, g2.x, g2.y, sLR4, sLA4);
    float4 o3 = process_row(x3, z3, p3, g3.x, g3.y, sLR4, sLA4);

    if (v0) out[r0] = o0;   // all STG.128 lane-contiguous
    if (v1) out[r1] = o1;
    if (v2) out[r2] = o2;
    if (v3) out[r3] = o3;
}

extern "C" void kernel_launch(void* const* d_in, const int* in_sizes, int n_in,
                              void* d_out, int out_size) {
    const float* agent = (const float*)d_in[0];   // [B,3]
    const float* goal = (const float*)d_in[1];    // [B,2]
    const float* radius_table = (const float*)d_in[2];
    const float* angle_table = (const float*)d_in[3];
    const float* W = (const float*)d_in[4];
    const float* b = (const float*)d_in[5];

    int n = in_sizes[0] / 3;    // B = 2,000,000

    precompute_tables_kernel<<<32, TPB>>>(radius_table, angle_table, W, b);

    int blocks = (n + ROWS_PER_BLOCK - 1) / ROWS_PER_BLOCK;   // 1954
    goal_position_kernel<<<blocks, TPB>>>(agent,
                                          (const float2*)goal,
                                          (float4*)d_out, n);
}

// round 16
// speedup vs baseline: 1.5222x; 1.1290x over previous
#include <cuda_runtime.h>
#include <math.h>

#define NUM_RADIUS 15
#define NUM_ANGLE 48
#define EMB 32
#define NUM_ACTIONS 4
#define TPB 256
#define ROWS_PER_BLOCK (TPB * 4)   // 1024

// LR[r] = (float4) logit contribution of radius bucket r
// LA[t] = (float4) logit contribution of angle bucket t (+ bias)
__device__ float4 g_LR4[NUM_RADIUS];
__device__ float4 g_LA4[NUM_ANGLE];

// Warp-per-output precompute: 252 outputs, one warp each (32 blocks x 8 warps).
__global__ void __launch_bounds__(TPB)
precompute_tables_kernel(const float* __restrict__ radius_table,
                         const float* __restrict__ angle_table,
                         const float* __restrict__ W,
                         const float* __restrict__ b) {
    int warp = (blockIdx.x * TPB + threadIdx.x) >> 5;   // 0..255
    int lane = threadIdx.x & 31;
    const int NLR = NUM_RADIUS * NUM_ACTIONS;   // 60
    const int NLA = NUM_ANGLE * NUM_ACTIONS;    // 192

    float v = 0.0f;
    bool is_lr = warp < NLR;
    bool is_la = !is_lr && warp < NLR + NLA;
    if (is_lr) {
        int row = warp >> 2, a = warp & 3;
        v = radius_table[row * EMB + lane] * W[lane * NUM_ACTIONS + a];
    } else if (is_la) {
        int k = warp - NLR;
        int row = k >> 2, a = k & 3;
        v = angle_table[row * EMB + lane] * W[(EMB + lane) * NUM_ACTIONS + a];
        if (lane == 0) v += b[a];
    }
    #pragma unroll
    for (int off = 16; off > 0; off >>= 1)
        v += __shfl_down_sync(0xffffffffu, v, off);

    if (lane == 0) {
        if (is_lr) ((float*)g_LR4)[warp] = v;
        else if (is_la) ((float*)g_LA4)[warp - NLR] = v;
    }
}

// Per-row pipeline with fused atan2: since hypot(dx,dz)=radius is already
// needed for the radius bucket, the half-angle reduction is
//   u = mn/(mx + radius) = t/(1+sqrt(1+t^2)),  u in [0, 0.4142]
// (ONE fast divide, no extra sqrt). Taylor atan(u) through u^13:
// truncation <= u^15/15 ~ 1.2e-7 rad; total angle error ~1e-6 rad.
__device__ __forceinline__ float4 process_row(float axp, float azp, float pose,
                                              float gx, float gz,
                                              const float4* __restrict__ sLR4,
                                              const float4* __restrict__ sLA4) {
    float dx = gx - axp;
    float dz = gz - azp;

    // radius bucket: max radius = sqrt(2)*50 ~ 70.7 < 75 -> r_idx <= 14, no clamp
    float radius = sqrtf(fmaf(dx, dx, dz * dz));
    int r_idx = (int)(radius * 0.2f);

    float ax = fabsf(dx), ay = fabsf(dz);
    float mn = fminf(ax, ay), mx = fmaxf(ax, ay);
    float u = __fdividef(mn, mx + radius);
    float s = u * u;
    float p = 0.07692307693f;                 //  1/13
    p = fmaf(p, s, -0.09090909091f);          // -1/11
    p = fmaf(p, s,  0.11111111111f);          //  1/9
    p = fmaf(p, s, -0.14285714286f);          // -1/7
    p = fmaf(p, s,  0.2f);                    //  1/5
    p = fmaf(p, s, -0.33333333333f);          // -1/3
    float atu = fmaf(p * s, u, u);            // atan(u)
    float a = 2.0f * atu;                     // atan(mn/mx)
    if (ay > ax) a = 1.57079632679f - a;
    if (dx < 0.0f) a = 3.14159265359f - a;
    a = (dz < 0.0f) ? -a : a;                 // atan2(dz, dx)

    // angle bucket: match reference rounding (separate mul then subs)
    float deg = __fmul_rn(a, 57.29577951308232f);
    float dtg = __fsub_rn(90.0f, deg);
    float f = __fsub_rn(dtg, pose);
    float ad = fmaf(-360.0f, floorf(f * 0.0027777778f), f);
    ad = fminf(fmaxf(ad, 0.0f), 359.99997f);  // forces t_idx in [0,47]
    int t_idx = (int)(ad * 0.13333334f);

    float4 lr = sLR4[r_idx];   // LDS.128
    float4 la = sLA4[t_idx];   // LDS.128
    float l0 = lr.x + la.x;
    float l1 = lr.y + la.y;
    float l2 = lr.z + la.z;
    float l3 = lr.w + la.w;

    // log_softmax WITHOUT max-shift: |logit| < ~1.5, exp cannot overflow.
    float e0 = __expf(l0);
    float e1 = __expf(l1);
    float e2 = __expf(l2);
    float e3 = __expf(l3);
    float lse = __logf(e0 + e1 + e2 + e3);

    return make_float4(l0 - lse, l1 - lse, l2 - lse, l3 - lse);
}

// Coalesced mapping: block owns rows [R, R+1024); thread t handles rows
// R+t, R+256+t, R+512+t, R+768+t. goal LDG.64 and out STG.128 are
// lane-contiguous. Full blocks (99.95%) take an unpredicated fast path.
__global__ void __launch_bounds__(TPB, 8)
goal_position_kernel(const float* __restrict__ agentF,   // [B*3]
                     const float2* __restrict__ goal2,   // [B]
                     float4* __restrict__ out,           // [B]
                     int n) {                             // B
    __shared__ float4 sLR4[NUM_RADIUS];
    __shared__ float4 sLA4[NUM_ANGLE];
    int t = threadIdx.x;
    if (t < NUM_RADIUS) sLR4[t] = g_LR4[t];
    if (t < NUM_ANGLE) sLA4[t] = g_LA4[t];
    __syncthreads();

    int R = blockIdx.x * ROWS_PER_BLOCK;
    int r0 = R + t;
    int r1 = r0 + TPB;
    int r2 = r1 + TPB;
    int r3 = r2 + TPB;

    if (R + ROWS_PER_BLOCK <= n) {
        // ---- fast path: no bounds checks ----
        float x0 = agentF[3*r0], z0 = agentF[3*r0+1], p0 = agentF[3*r0+2];
        float x1 = agentF[3*r1], z1 = agentF[3*r1+1], p1 = agentF[3*r1+2];
        float x2 = agentF[3*r2], z2 = agentF[3*r2+1], p2 = agentF[3*r2+2];
        float x3 = agentF[3*r3], z3 = agentF[3*r3+1], p3 = agentF[3*r3+2];
        float2 g0 = goal2[r0], g1 = goal2[r1], g2 = goal2[r2], g3 = goal2[r3];

        float4 o0 = process_row(x0, z0, p0, g0.x, g0.y, sLR4, sLA4);
        float4 o1 = process_row(x1, z1, p1, g1.x, g1.y, sLR4, sLA4);
        float4 o2 = process_row(x2, z2, p2, g2.x, g2.y, sLR4, sLA4);
        float4 o3 = process_row(x3, z3, p3, g3.x, g3.y, sLR4, sLA4);

        out[r0] = o0;
        out[r1] = o1;
        out[r2] = o2;
        out[r3] = o3;
    } else {
        // ---- tail path: guarded (last block only) ----
        #pragma unroll
        for (int k = 0; k < 4; k++) {
            int r = R + k * TPB + t;
            if (r < n) {
                float x = agentF[3*r], z = agentF[3*r+1], pz = agentF[3*r+2];
                float2 g = goal2[r];
                out[r] = process_row(x, z, pz, g.x, g.y, sLR4, sLA4);
            }
        }
    }
}

extern "C" void kernel_launch(void* const* d_in, const int* in_sizes, int n_in,
                              void* d_out, int out_size) {
    const float* agent = (const float*)d_in[0];   // [B,3]
    const float* goal = (const float*)d_in[1];    // [B,2]
    const float* radius_table = (const float*)d_in[2];
    const float* angle_table = (const float*)d_in[3];
    const float* W = (const float*)d_in[4];
    const float* b = (const float*)d_in[5];

    int n = in_sizes[0] / 3;    // B = 2,000,000

    precompute_tables_kernel<<<32, TPB>>>(radius_table, angle_table, W, b);

    int blocks = (n + ROWS_PER_BLOCK - 1) / ROWS_PER_BLOCK;   // 1954
    goal_position_kernel<<<blocks, TPB>>>(agent,
                                          (const float2*)goal,
                                          (float4*)d_out, n);
}